// round 5
// baseline (speedup 1.0000x reference)
#include <cuda_runtime.h>
#include <cuda_bf16.h>

// ---------------- problem constants ----------------
#define BB   16384            // batch
#define HH   256              // hidden
#define SS   4                // feature
#define TOBS 16               // encoder timesteps
#define TOUT 16               // decoder timesteps
#define BH   (BB * HH)        // 4,194,304

// ---------------- GEMM tiling ----------------
#define MT   64               // batch rows per block
#define NT   64               // per-gate cols per block (block covers 4*NT gate cols)
#define KT   16               // k tile
#define NTH  256              // threads per block
#define HSP  (MT + 4)         // padded Hs row stride (68 floats, 16B-aligned)

// ---------------- device scratch (allocation-free rule: __device__ globals) ----
__device__ float g_eh[2][2][BH];   // encoder h ping-pong [net][p]
__device__ float g_ec[2][BH];      // encoder c (in-place safe)
__device__ float g_dh[2][2][BH];   // decoder h ping-pong
__device__ float g_dc[2][BH];      // decoder c
__device__ float g_dx[2][BB * SS]; // decoder feedback inputs

struct Net {
    const float* __restrict__ Wih;   // [1024,4]
    const float* __restrict__ Whh;   // [1024,256]
    const float* __restrict__ bih;   // [1024]
    const float* __restrict__ bhh;   // [1024]
    const float* __restrict__ x;     // input rows
    int xstride;                     // floats between consecutive batch rows
    const float* __restrict__ h_in;  // [B,H]
    float* __restrict__ c;           // [B,H] in-place
    float* __restrict__ h_out;       // [B,H]
};

__device__ __forceinline__ float sigf(float x) {
    return 1.0f / (1.0f + __expf(-x));
}
__device__ __forceinline__ float tanh_acc(float x) {
    // 2*sigmoid(2x)-1 : EX2+RCP, abs err ~1e-7, saturates to +/-1 correctly
    return 2.0f / (1.0f + __expf(-2.0f * x)) - 1.0f;
}

// ================= fused LSTM step: G = h@Whh^T + x@Wih^T + b ; update c,h ===
__global__ void __launch_bounds__(NTH, 2)
lstm_step_kernel(Net n0, Net n1)
{
    Net P = (blockIdx.z == 0) ? n0 : n1;

    __shared__ float  Ws[KT][4 * NT];   // [k][gatecol] 16KB
    __shared__ float  Hs[KT][HSP];      // [k][m]       4.25KB
    __shared__ float4 WihS[4 * NT];     // Wih rows for this block's 256 gate cols
    __shared__ float  biasS[4 * NT];
    __shared__ float4 Xs[MT];           // x rows

    const int tid = threadIdx.x;
    const int tx  = tid & 15;          // n group (4 cols per gate)
    const int ty  = tid >> 4;          // m group (4 rows)
    const int m0  = blockIdx.y * MT;
    const int nb0 = blockIdx.x * NT;

    // gate-column owned by this thread for staging: ln = tid
    const int gsel = tid >> 6;               // gate 0..3
    const int col  = tid & 63;               // col within gate tile
    const int j    = gsel * 256 + nb0 + col; // global gate column

    // ---- prologue: small operands ----
    WihS[tid]  = *(const float4*)(P.Wih + j * 4);
    biasS[tid] = P.bih[j] + P.bhh[j];
    if (tid < MT) {
        Xs[tid] = *(const float4*)(P.x + (size_t)(m0 + tid) * P.xstride);
    }

    float acc[4][16];
    #pragma unroll
    for (int a = 0; a < 4; a++)
        #pragma unroll
        for (int q = 0; q < 16; q++) acc[a][q] = 0.0f;

    const float* wr = P.Whh + (size_t)j * HH;
    const int hr = tid & 63;   // h row for staging
    const int kq = tid >> 6;   // k quarter

    for (int kt = 0; kt < HH / KT; kt++) {
        const int k0 = kt * KT;
        // stage Whh tile transposed: Ws[k][ln]
        #pragma unroll
        for (int q = 0; q < 4; q++) {
            float4 w = *(const float4*)(wr + k0 + q * 4);
            Ws[q * 4 + 0][tid] = w.x;
            Ws[q * 4 + 1][tid] = w.y;
            Ws[q * 4 + 2][tid] = w.z;
            Ws[q * 4 + 3][tid] = w.w;
        }
        // stage h tile transposed: Hs[k][m]
        {
            float4 h4 = *(const float4*)(P.h_in + (size_t)(m0 + hr) * HH + k0 + kq * 4);
            Hs[kq * 4 + 0][hr] = h4.x;
            Hs[kq * 4 + 1][hr] = h4.y;
            Hs[kq * 4 + 2][hr] = h4.z;
            Hs[kq * 4 + 3][hr] = h4.w;
        }
        __syncthreads();

        #pragma unroll
        for (int kk = 0; kk < KT; kk++) {
            float4 hv = *(const float4*)&Hs[kk][ty * 4];
            float4 w0 = *(const float4*)&Ws[kk][0   + tx * 4];
            float4 w1 = *(const float4*)&Ws[kk][64  + tx * 4];
            float4 w2 = *(const float4*)&Ws[kk][128 + tx * 4];
            float4 w3 = *(const float4*)&Ws[kk][192 + tx * 4];
            float hm[4] = {hv.x, hv.y, hv.z, hv.w};
            float wv[16] = {w0.x, w0.y, w0.z, w0.w,
                            w1.x, w1.y, w1.z, w1.w,
                            w2.x, w2.y, w2.z, w2.w,
                            w3.x, w3.y, w3.z, w3.w};
            #pragma unroll
            for (int mi = 0; mi < 4; mi++)
                #pragma unroll
                for (int q = 0; q < 16; q++)
                    acc[mi][q] += hm[mi] * wv[q];
        }
        __syncthreads();
    }

    // ---- epilogue: add x@Wih^T + bias, apply LSTM cell, write c,h ----
    const int r0 = ty * 4;
    #pragma unroll
    for (int mi = 0; mi < 4; mi++) {
        const int b = m0 + r0 + mi;
        float4 xr = Xs[r0 + mi];
        float gate[4][4];
        #pragma unroll
        for (int g = 0; g < 4; g++) {
            #pragma unroll
            for (int e = 0; e < 4; e++) {
                int ln = g * 64 + tx * 4 + e;
                float4 wi = WihS[ln];
                gate[g][e] = acc[mi][g * 4 + e] + biasS[ln]
                           + xr.x * wi.x + xr.y * wi.y + xr.z * wi.z + xr.w * wi.w;
            }
        }
        float* cp = P.c + (size_t)b * HH + nb0 + tx * 4;
        float4 cold = *(const float4*)cp;
        float cv[4] = {cold.x, cold.y, cold.z, cold.w};
        float cn[4], hn[4];
        #pragma unroll
        for (int e = 0; e < 4; e++) {
            float ig = sigf(gate[0][e]);
            float fg = sigf(gate[1][e]);
            float gg = tanh_acc(gate[2][e]);
            float og = sigf(gate[3][e]);
            cn[e] = fg * cv[e] + ig * gg;
            hn[e] = og * tanh_acc(cn[e]);
        }
        *(float4*)cp = make_float4(cn[0], cn[1], cn[2], cn[3]);
        *(float4*)(P.h_out + (size_t)b * HH + nb0 + tx * 4)
            = make_float4(hn[0], hn[1], hn[2], hn[3]);
    }
}

// ================= zero-init encoder state =================
__global__ void zero_state_kernel(float* a, float* b, float* c, float* d)
{
    int i = blockIdx.x * blockDim.x + threadIdx.x;
    a[i] = 0.0f; b[i] = 0.0f; c[i] = 0.0f; d[i] = 0.0f;
}

// ======== combine encoder states into both decoders; seed feedback x ========
__global__ void combine_kernel(const float* __restrict__ speed,
                               const float* __restrict__ pos)
{
    int i = blockIdx.x * blockDim.x + threadIdx.x;
    float hv = g_eh[0][0][i] + g_eh[1][0][i];
    float cv = g_ec[0][i] + g_ec[1][i];
    g_dh[0][0][i] = hv; g_dh[1][0][i] = hv;
    g_dc[0][i]    = cv; g_dc[1][i]    = cv;
    if (i < BB * SS) {
        int b = i >> 2, s = i & 3;
        // seq[:, -1, :]  (t = 15)
        g_dx[0][i] = speed[b * (TOBS * SS) + 15 * SS + s];
        g_dx[1][i] = pos  [b * (TOBS * SS) + 15 * SS + s];
    }
}

// ================= decoder heads: one warp per batch row =================
__global__ void dec_head_kernel(const float* __restrict__ hsp,
                                const float* __restrict__ hcr,
                                const float* __restrict__ fcW, const float* __restrict__ fcb,
                                const float* __restrict__ crW, const float* __restrict__ crb,
                                const float* __restrict__ emW, const float* __restrict__ emb,
                                float* __restrict__ out_sp, float* __restrict__ out_cr,
                                int t)
{
    __shared__ float Wsm[10][HH];
    __shared__ float bsm[10];
    int tid = threadIdx.x;
    #pragma unroll
    for (int rr = 0; rr < 10; rr++) {
        const float* src = (rr < 4) ? fcW + rr * HH
                         : (rr < 6) ? crW + (rr - 4) * HH
                                    : emW + (rr - 6) * HH;
        Wsm[rr][tid] = src[tid];
    }
    if (tid < 10)
        bsm[tid] = (tid < 4) ? fcb[tid] : (tid < 6) ? crb[tid - 4] : emb[tid - 6];
    __syncthreads();

    int lane = tid & 31;
    int b = blockIdx.x * 8 + (tid >> 5);

    // ---- speed head ----
    float v[8];
    #pragma unroll
    for (int jq = 0; jq < 8; jq++) v[jq] = hsp[(size_t)b * HH + lane + jq * 32];
    float dsp[4];
    #pragma unroll
    for (int r = 0; r < 4; r++) {
        float p = 0.0f;
        #pragma unroll
        for (int jq = 0; jq < 8; jq++) p += v[jq] * Wsm[r][lane + jq * 32];
        #pragma unroll
        for (int o = 16; o; o >>= 1) p += __shfl_xor_sync(0xffffffffu, p, o);
        dsp[r] = p;
    }
    if (lane < 4) {
        float ov = fminf(fmaxf(dsp[lane] + bsm[lane], -100.0f), 100.0f);
        out_sp[(size_t)b * (TOUT * SS) + t * SS + lane] = ov;
        g_dx[0][b * SS + lane] = ov;   // feedback to speed decoder
    }

    // ---- crossing head ----
    float u[8];
    #pragma unroll
    for (int jq = 0; jq < 8; jq++) u[jq] = hcr[(size_t)b * HH + lane + jq * 32];
    float dcr[6];
    #pragma unroll
    for (int r = 0; r < 6; r++) {
        float p = 0.0f;
        #pragma unroll
        for (int jq = 0; jq < 8; jq++) p += u[jq] * Wsm[4 + r][lane + jq * 32];
        #pragma unroll
        for (int o = 16; o; o >>= 1) p += __shfl_xor_sync(0xffffffffu, p, o);
        dcr[r] = p;
    }
    float l0 = fmaxf(dcr[0] + bsm[4], 0.0f);
    float l1 = fmaxf(dcr[1] + bsm[5], 0.0f);
    float mx = fmaxf(l0, l1);
    float e0 = __expf(l0 - mx), e1 = __expf(l1 - mx);
    float inv = 1.0f / (e0 + e1);
    if (lane == 0) {
        out_cr[(size_t)b * (TOUT * 2) + t * 2 + 0] = e0 * inv;
        out_cr[(size_t)b * (TOUT * 2) + t * 2 + 1] = e1 * inv;
    }
    if (lane < 4) {
        g_dx[1][b * SS + lane] = fmaxf(dcr[2 + lane] + bsm[6 + lane], 0.0f);
    }
}

// =========================== host orchestration ===========================
extern "C" void kernel_launch(void* const* d_in, const int* in_sizes, int n_in,
                              void* d_out, int out_size)
{
    const float* speed   = (const float*)d_in[0];
    const float* pos     = (const float*)d_in[1];
    const float* sp_Wih  = (const float*)d_in[2];
    const float* sp_Whh  = (const float*)d_in[3];
    const float* sp_bih  = (const float*)d_in[4];
    const float* sp_bhh  = (const float*)d_in[5];
    const float* po_Wih  = (const float*)d_in[6];
    const float* po_Whh  = (const float*)d_in[7];
    const float* po_bih  = (const float*)d_in[8];
    const float* po_bhh  = (const float*)d_in[9];
    const float* dsp_Wih = (const float*)d_in[10];
    const float* dsp_Whh = (const float*)d_in[11];
    const float* dsp_bih = (const float*)d_in[12];
    const float* dsp_bhh = (const float*)d_in[13];
    const float* dcr_Wih = (const float*)d_in[14];
    const float* dcr_Whh = (const float*)d_in[15];
    const float* dcr_bih = (const float*)d_in[16];
    const float* dcr_bhh = (const float*)d_in[17];
    const float* fcW     = (const float*)d_in[18];
    const float* fcb     = (const float*)d_in[19];
    const float* crW     = (const float*)d_in[20];
    const float* crb     = (const float*)d_in[21];
    const float* emW     = (const float*)d_in[22];
    const float* emb     = (const float*)d_in[23];

    float *eh, *ec, *dh, *dc, *dx;
    cudaGetSymbolAddress((void**)&eh, g_eh);
    cudaGetSymbolAddress((void**)&ec, g_ec);
    cudaGetSymbolAddress((void**)&dh, g_dh);
    cudaGetSymbolAddress((void**)&dc, g_dc);
    cudaGetSymbolAddress((void**)&dx, g_dx);

    float* out_sp = (float*)d_out;
    float* out_cr = out_sp + (size_t)BB * TOUT * SS;

    const dim3 sgrid(HH / NT, BB / MT, 2);   // (4, 256, 2)

    // 1) zero encoder initial state (h ping0, c)
    zero_state_kernel<<<BH / NTH, NTH>>>(eh + 0 * BH, eh + 2 * BH,
                                         ec + 0 * BH, ec + 1 * BH);

    // 2) encoders, 16 steps, both nets per launch
    for (int t = 0; t < TOBS; t++) {
        int pi = t & 1, po_ = (t + 1) & 1;
        Net a0 = { sp_Wih, sp_Whh, sp_bih, sp_bhh,
                   speed + t * SS, TOBS * SS,
                   eh + (0 * 2 + pi) * BH, ec + 0 * BH, eh + (0 * 2 + po_) * BH };
        Net a1 = { po_Wih, po_Whh, po_bih, po_bhh,
                   pos + t * SS, TOBS * SS,
                   eh + (1 * 2 + pi) * BH, ec + 1 * BH, eh + (1 * 2 + po_) * BH };
        lstm_step_kernel<<<sgrid, NTH>>>(a0, a1);
    }

    // 3) combine into decoder state + seed feedback inputs
    combine_kernel<<<BH / NTH, NTH>>>(speed, pos);

    // 4) decoders, 16 steps (step + head per step)
    for (int t = 0; t < TOUT; t++) {
        int pi = t & 1, po_ = (t + 1) & 1;
        Net a0 = { dsp_Wih, dsp_Whh, dsp_bih, dsp_bhh,
                   dx + 0 * (BB * SS), SS,
                   dh + (0 * 2 + pi) * BH, dc + 0 * BH, dh + (0 * 2 + po_) * BH };
        Net a1 = { dcr_Wih, dcr_Whh, dcr_bih, dcr_bhh,
                   dx + 1 * (BB * SS), SS,
                   dh + (1 * 2 + pi) * BH, dc + 1 * BH, dh + (1 * 2 + po_) * BH };
        lstm_step_kernel<<<sgrid, NTH>>>(a0, a1);

        dec_head_kernel<<<BB / 8, NTH>>>(dh + (0 * 2 + po_) * BH,
                                         dh + (1 * 2 + po_) * BH,
                                         fcW, fcb, crW, crb, emW, emb,
                                         out_sp, out_cr, t);
    }
}